// round 6
// baseline (speedup 1.0000x reference)
#include <cuda_runtime.h>
#include <cstdint>
#include <math.h>

// PatchRepulsionLoss: pcs [8192, 2048, 3] f32 -> scalar f32
// B=8192, P=32 patches, n=64 pts/patch, N_SIGMA=1
// loss = sum_b sum_{i<=j} || relu(std_i+std_j - |mean_i-mean_j|) ||_2 / (528*B)
//
// Pair identity: std_i+std_j - |m_i-m_j| = min(hi_j - lo_i, hi_i - lo_j),
// hi = mean+std, lo = mean-std.
//
// Single-kernel: CTAs accumulate into __device__ scratch, last CTA writes
// d_out and resets scratch (deterministic across graph replays).

#define NPATCH 32
#define NBATCH 8192
#define NTHREADS 256
#define CHUNK_BYTES 12288            // 16 patches
#define BATCH_BYTES (2 * CHUNK_BYTES)

__device__ float g_partial;          // zero at module load; reset each run
__device__ unsigned int g_done;      // zero at module load; reset each run

__device__ __forceinline__ uint32_t smem_u32(const void* p) {
    uint32_t a;
    asm("{ .reg .u64 t; cvta.to.shared.u64 t, %1; cvt.u32.u64 %0, t; }"
        : "=r"(a) : "l"(p));
    return a;
}

__device__ __forceinline__ void bulk_copy(uint32_t dst, const void* src,
                                          uint32_t bytes, uint32_t mbar) {
    asm volatile("mbarrier.arrive.expect_tx.shared.b64 _, [%0], %1;"
                 :: "r"(mbar), "r"(bytes) : "memory");
    asm volatile(
        "cp.async.bulk.shared::cta.global.mbarrier::complete_tx::bytes "
        "[%0], [%1], %2, [%3];"
        :: "r"(dst), "l"(src), "r"(bytes), "r"(mbar) : "memory");
}

__device__ __forceinline__ void mbar_wait0(uint32_t mbar) {
    uint32_t done;
    asm volatile(
        "{\n\t.reg .pred p;\n\t"
        "mbarrier.try_wait.parity.acquire.cta.shared::cta.b64 p, [%1], 0;\n\t"
        "selp.b32 %0, 1, 0, p;\n\t}"
        : "=r"(done) : "r"(mbar) : "memory");
    if (!done) {
        asm volatile(
            "{\n\t.reg .pred P1;\n\t"
            "WL_%=:\n\t"
            "mbarrier.try_wait.parity.acquire.cta.shared::cta.b64 P1, [%0], 0, 0x989680;\n\t"
            "@P1 bra.uni WD_%=;\n\t"
            "bra.uni WL_%=;\n\t"
            "WD_%=:\n\t}"
            :: "r"(mbar) : "memory");
    }
}

__device__ __forceinline__ float sqrt_approx(float x) {
    float r;
    asm("sqrt.approx.f32 %0, %1;" : "=f"(r) : "f"(x));
    return r;
}

__global__ void __launch_bounds__(NTHREADS, 8)
prl_main_kernel(const float* __restrict__ pcs, float* __restrict__ out) {
    __shared__ alignas(128) float4 sbuf[1536];          // 24 KB, halves at 0/768
    __shared__ alignas(8) uint64_t mbar[2];
    __shared__ float s_lo[3 * NPATCH];                  // SoA [d][patch]
    __shared__ float s_hi[3 * NPATCH];
    __shared__ float s_part[8];

    const int tid = threadIdx.x;
    const int lane = tid & 31;
    const int warp = tid >> 5;
    const int half = tid >> 7;          // warps 0-3 -> chunk0, 4-7 -> chunk1
    const int tl = tid & 127;
    const uint32_t mb = smem_u32(&mbar[half]);
    const uint32_t sbase = smem_u32(sbuf);

    if (tid == 0) {
        asm volatile("mbarrier.init.shared.b64 [%0], 1;" :: "r"(smem_u32(&mbar[0])) : "memory");
        asm volatile("mbarrier.init.shared.b64 [%0], 1;" :: "r"(smem_u32(&mbar[1])) : "memory");
        const char* src = reinterpret_cast<const char*>(pcs) +
                          (size_t)blockIdx.x * BATCH_BYTES;
        bulk_copy(sbase, src, CHUNK_BYTES, smem_u32(&mbar[0]));
        bulk_copy(sbase + CHUNK_BYTES, src + CHUNK_BYTES, CHUNK_BYTES,
                  smem_u32(&mbar[1]));
    }
    __syncthreads();   // mbarrier inits visible before any wait

    mbar_wait0(mb);

    // ---- Stats: thread owns f4[6*tl .. 6*tl+5] of its half (24 consecutive
    // floats, phase 0). Loads permuted by delta=(lane>>2)&1 for bank-conflict
    // freedom; delta rotates the dim frame by +delta, undone via SELs below.
    const int delta = (lane >> 2) & 1;
    // packed accumulators: pair types (d0,d1),(d2,d0),(d1,d2) in delta-frame
    uint64_t S01 = 0, S20 = 0, S12 = 0;
    uint64_t Q01 = 0, Q20 = 0, Q12 = 0;
    const uint32_t tbase = sbase + (uint32_t)half * CHUNK_BYTES + (uint32_t)tl * 96;

#pragma unroll
    for (int j = 0; j < 6; j++) {
        int m = j + delta; if (m >= 6) m -= 6;
        uint64_t plo, phi;   // plo=(e0,e1), phi=(e2,e3); f4 start phase = j mod 3 (frame)
        asm("ld.shared.v2.b64 {%0,%1}, [%2];"
            : "=l"(plo), "=l"(phi) : "r"(tbase + (uint32_t)(m * 16)));
        if (j % 3 == 0) {      // pairs (0,1),(2,0)
            asm("add.rn.f32x2 %0,%0,%1;" : "+l"(S01) : "l"(plo));
            asm("add.rn.f32x2 %0,%0,%1;" : "+l"(S20) : "l"(phi));
            asm("fma.rn.f32x2 %0,%1,%1,%0;" : "+l"(Q01) : "l"(plo));
            asm("fma.rn.f32x2 %0,%1,%1,%0;" : "+l"(Q20) : "l"(phi));
        } else if (j % 3 == 1) { // pairs (1,2),(0,1)
            asm("add.rn.f32x2 %0,%0,%1;" : "+l"(S12) : "l"(plo));
            asm("add.rn.f32x2 %0,%0,%1;" : "+l"(S01) : "l"(phi));
            asm("fma.rn.f32x2 %0,%1,%1,%0;" : "+l"(Q12) : "l"(plo));
            asm("fma.rn.f32x2 %0,%1,%1,%0;" : "+l"(Q01) : "l"(phi));
        } else {                 // pairs (2,0),(1,2)
            asm("add.rn.f32x2 %0,%0,%1;" : "+l"(S20) : "l"(plo));
            asm("add.rn.f32x2 %0,%0,%1;" : "+l"(S12) : "l"(phi));
            asm("fma.rn.f32x2 %0,%1,%1,%0;" : "+l"(Q20) : "l"(plo));
            asm("fma.rn.f32x2 %0,%1,%1,%0;" : "+l"(Q12) : "l"(phi));
        }
    }

    // unpack: frame-dim sums  f0=S01.lo+S20.hi  f1=S01.hi+S12.lo  f2=S20.lo+S12.hi
    float a0l, a0h, a1l, a1h, a2l, a2h;
    asm("mov.b64 {%0,%1}, %2;" : "=f"(a0l), "=f"(a0h) : "l"(S01));
    asm("mov.b64 {%0,%1}, %2;" : "=f"(a1l), "=f"(a1h) : "l"(S20));
    asm("mov.b64 {%0,%1}, %2;" : "=f"(a2l), "=f"(a2h) : "l"(S12));
    float fs0 = a0l + a1h, fs1 = a0h + a2l, fs2 = a1l + a2h;
    asm("mov.b64 {%0,%1}, %2;" : "=f"(a0l), "=f"(a0h) : "l"(Q01));
    asm("mov.b64 {%0,%1}, %2;" : "=f"(a1l), "=f"(a1h) : "l"(Q20));
    asm("mov.b64 {%0,%1}, %2;" : "=f"(a2l), "=f"(a2h) : "l"(Q12));
    float fq0 = a0l + a1h, fq1 = a0h + a2l, fq2 = a1l + a2h;

    // un-rotate: frame slot f holds actual dim (f+delta)%3
    float s0 = delta ? fs2 : fs0;
    float s1 = delta ? fs0 : fs1;
    float s2 = delta ? fs1 : fs2;
    float q0 = delta ? fq2 : fq0;
    float q1 = delta ? fq0 : fq1;
    float q2 = delta ? fq1 : fq2;

    // 8-lane group reduce (threads 8p..8p+7 own patch p of this half)
#pragma unroll
    for (int off = 4; off; off >>= 1) {
        s0 += __shfl_xor_sync(0xFFFFFFFFu, s0, off);
        s1 += __shfl_xor_sync(0xFFFFFFFFu, s1, off);
        s2 += __shfl_xor_sync(0xFFFFFFFFu, s2, off);
        q0 += __shfl_xor_sync(0xFFFFFFFFu, q0, off);
        q1 += __shfl_xor_sync(0xFFFFFFFFu, q1, off);
        q2 += __shfl_xor_sync(0xFFFFFFFFu, q2, off);
    }
    if ((tl & 7) == 0) {
        const int gp = half * 16 + (tl >> 3);
        const float inv_n = 1.0f / 64.0f;
        const float inv_nm1 = 1.0f / 63.0f;
        float m0 = s0 * inv_n, m1 = s1 * inv_n, m2 = s2 * inv_n;
        float sd0 = sqrt_approx(fmaxf((q0 - s0 * m0) * inv_nm1, 0.0f));
        float sd1 = sqrt_approx(fmaxf((q1 - s1 * m1) * inv_nm1, 0.0f));
        float sd2 = sqrt_approx(fmaxf((q2 - s2 * m2) * inv_nm1, 0.0f));
        s_lo[0 * NPATCH + gp] = m0 - sd0;
        s_lo[1 * NPATCH + gp] = m1 - sd1;
        s_lo[2 * NPATCH + gp] = m2 - sd2;
        s_hi[0 * NPATCH + gp] = m0 + sd0;
        s_hi[1 * NPATCH + gp] = m1 + sd1;
        s_hi[2 * NPATCH + gp] = m2 + sd2;
    }
    __syncthreads();

    // ---- Pair phase: full 32x32 symmetric; upper-tri incl diag =
    // 0.5*full + 0.5*diag -> weight 0.5 off-diag, 1.0 on diag.
    // j = lane stats hoisted to registers; i = warp + 8k uniform (broadcast LDS).
    const float jlo0 = s_lo[0 * NPATCH + lane];
    const float jlo1 = s_lo[1 * NPATCH + lane];
    const float jlo2 = s_lo[2 * NPATCH + lane];
    const float jhi0 = s_hi[0 * NPATCH + lane];
    const float jhi1 = s_hi[1 * NPATCH + lane];
    const float jhi2 = s_hi[2 * NPATCH + lane];

    float local = 0.0f;
#pragma unroll
    for (int k = 0; k < 4; k++) {
        const int i = warp + 8 * k;          // uniform within warp
        const float ilo0 = s_lo[0 * NPATCH + i];
        const float ilo1 = s_lo[1 * NPATCH + i];
        const float ilo2 = s_lo[2 * NPATCH + i];
        const float ihi0 = s_hi[0 * NPATCH + i];
        const float ihi1 = s_hi[1 * NPATCH + i];
        const float ihi2 = s_hi[2 * NPATCH + i];
        float r0 = fmaxf(fminf(ihi0 - jlo0, jhi0 - ilo0), 0.0f);
        float r1 = fmaxf(fminf(ihi1 - jlo1, jhi1 - ilo1), 0.0f);
        float r2 = fmaxf(fminf(ihi2 - jlo2, jhi2 - ilo2), 0.0f);
        float acc = fmaf(r0, r0, fmaf(r1, r1, r2 * r2));
        float nrm = sqrt_approx(acc);
        local += (i == lane) ? nrm : 0.5f * nrm;
    }

    // ---- Block reduce + scratch accumulate; last CTA finalizes ----
#pragma unroll
    for (int off = 16; off; off >>= 1)
        local += __shfl_xor_sync(0xFFFFFFFFu, local, off);
    if (lane == 0) s_part[warp] = local;
    __syncthreads();
    if (tid == 0) {
        float v = s_part[0] + s_part[1] + s_part[2] + s_part[3] +
                  s_part[4] + s_part[5] + s_part[6] + s_part[7];
        const float scale = 1.0f / (528.0f * (float)NBATCH);
        atomicAdd(&g_partial, v * scale);
        __threadfence();
        unsigned int prev = atomicAdd(&g_done, 1u);
        if (prev == (unsigned int)(NBATCH - 1)) {
            // all CTAs' g_partial adds are visible (fence-before-count order)
            out[0] = g_partial;
            // reset for the next graph replay (deterministic across calls)
            g_partial = 0.0f;
            g_done = 0u;
            __threadfence();
        }
    }
}

extern "C" void kernel_launch(void* const* d_in, const int* in_sizes, int n_in,
                              void* d_out, int out_size) {
    const float* pcs = (const float*)d_in[0];
    float* out = (float*)d_out;
    prl_main_kernel<<<NBATCH, NTHREADS>>>(pcs, out);
}

// round 7
// speedup vs baseline: 1.0314x; 1.0314x over previous
#include <cuda_runtime.h>
#include <cstdint>
#include <math.h>

// PatchRepulsionLoss: pcs [8192, 2048, 3] f32 -> scalar f32
// B=8192, P=32 patches, n=64 pts/patch, N_SIGMA=1
// loss = sum_b sum_{i<=j} || relu(std_i+std_j - |mean_i-mean_j|) ||_2 / (528*B)
//
// Pair identity: std_i+std_j - |m_i-m_j| = min(hi_j - lo_i, hi_i - lo_j),
// hi = mean+std, lo = mean-std.
//
// Single-kernel finalize via release/acquire atomics (no __threadfence, no
// L1 flush): CTAs RED.ADD into g_partial, release-add a done counter; the
// last CTA acquire-loads the total, writes d_out, and resets scratch.

#define NPATCH 32
#define NBATCH 8192
#define NTHREADS 256
#define CHUNK_BYTES 12288            // 16 patches
#define BATCH_BYTES (2 * CHUNK_BYTES)

__device__ float g_partial;          // zero at load; reset by last CTA each run
__device__ unsigned int g_done;      // zero at load; reset by last CTA each run

__device__ __forceinline__ uint32_t smem_u32(const void* p) {
    uint32_t a;
    asm("{ .reg .u64 t; cvta.to.shared.u64 t, %1; cvt.u32.u64 %0, t; }"
        : "=r"(a) : "l"(p));
    return a;
}

__device__ __forceinline__ void bulk_copy(uint32_t dst, const void* src,
                                          uint32_t bytes, uint32_t mbar) {
    asm volatile("mbarrier.arrive.expect_tx.shared.b64 _, [%0], %1;"
                 :: "r"(mbar), "r"(bytes) : "memory");
    asm volatile(
        "cp.async.bulk.shared::cta.global.mbarrier::complete_tx::bytes "
        "[%0], [%1], %2, [%3];"
        :: "r"(dst), "l"(src), "r"(bytes), "r"(mbar) : "memory");
}

__device__ __forceinline__ void mbar_wait0(uint32_t mbar) {
    uint32_t done;
    asm volatile(
        "{\n\t.reg .pred p;\n\t"
        "mbarrier.try_wait.parity.acquire.cta.shared::cta.b64 p, [%1], 0;\n\t"
        "selp.b32 %0, 1, 0, p;\n\t}"
        : "=r"(done) : "r"(mbar) : "memory");
    if (!done) {
        asm volatile(
            "{\n\t.reg .pred P1;\n\t"
            "WL_%=:\n\t"
            "mbarrier.try_wait.parity.acquire.cta.shared::cta.b64 P1, [%0], 0, 0x989680;\n\t"
            "@P1 bra.uni WD_%=;\n\t"
            "bra.uni WL_%=;\n\t"
            "WD_%=:\n\t}"
            :: "r"(mbar) : "memory");
    }
}

__device__ __forceinline__ float sqrt_approx(float x) {
    float r;
    asm("sqrt.approx.f32 %0, %1;" : "=f"(r) : "f"(x));
    return r;
}

__global__ void __launch_bounds__(NTHREADS, 8)
prl_main_kernel(const float* __restrict__ pcs, float* __restrict__ out) {
    __shared__ alignas(128) float4 sbuf[1536];          // 24 KB, halves at 0/768
    __shared__ alignas(8) uint64_t mbar[2];
    __shared__ float s_lo[3 * NPATCH];                  // SoA [d][patch]
    __shared__ float s_hi[3 * NPATCH];
    __shared__ float s_part[8];

    const int tid = threadIdx.x;
    const int lane = tid & 31;
    const int warp = tid >> 5;
    const int half = tid >> 7;          // warps 0-3 -> chunk0, 4-7 -> chunk1
    const int tl = tid & 127;
    const uint32_t mb = smem_u32(&mbar[half]);
    const uint32_t sbase = smem_u32(sbuf);

    if (tid == 0) {
        asm volatile("mbarrier.init.shared.b64 [%0], 1;" :: "r"(smem_u32(&mbar[0])) : "memory");
        asm volatile("mbarrier.init.shared.b64 [%0], 1;" :: "r"(smem_u32(&mbar[1])) : "memory");
        const char* src = reinterpret_cast<const char*>(pcs) +
                          (size_t)blockIdx.x * BATCH_BYTES;
        bulk_copy(sbase, src, CHUNK_BYTES, smem_u32(&mbar[0]));
        bulk_copy(sbase + CHUNK_BYTES, src + CHUNK_BYTES, CHUNK_BYTES,
                  smem_u32(&mbar[1]));
    }
    __syncthreads();   // mbarrier inits visible before any wait

    mbar_wait0(mb);

    // ---- Stats: thread owns f4[6*tl .. 6*tl+5] of its half (24 consecutive
    // floats, phase 0). Loads permuted by delta=(lane>>2)&1 for bank-conflict
    // freedom; delta rotates the dim frame by +delta, undone via SELs below.
    const int delta = (lane >> 2) & 1;
    // packed accumulators: pair types (d0,d1),(d2,d0),(d1,d2) in delta-frame
    uint64_t S01 = 0, S20 = 0, S12 = 0;
    uint64_t Q01 = 0, Q20 = 0, Q12 = 0;
    const uint32_t tbase = sbase + (uint32_t)half * CHUNK_BYTES + (uint32_t)tl * 96;

#pragma unroll
    for (int j = 0; j < 6; j++) {
        int m = j + delta; if (m >= 6) m -= 6;
        uint64_t plo, phi;   // plo=(e0,e1), phi=(e2,e3); f4 start phase = j mod 3 (frame)
        asm("ld.shared.v2.b64 {%0,%1}, [%2];"
            : "=l"(plo), "=l"(phi) : "r"(tbase + (uint32_t)(m * 16)));
        if (j % 3 == 0) {      // pairs (0,1),(2,0)
            asm("add.rn.f32x2 %0,%0,%1;" : "+l"(S01) : "l"(plo));
            asm("add.rn.f32x2 %0,%0,%1;" : "+l"(S20) : "l"(phi));
            asm("fma.rn.f32x2 %0,%1,%1,%0;" : "+l"(Q01) : "l"(plo));
            asm("fma.rn.f32x2 %0,%1,%1,%0;" : "+l"(Q20) : "l"(phi));
        } else if (j % 3 == 1) { // pairs (1,2),(0,1)
            asm("add.rn.f32x2 %0,%0,%1;" : "+l"(S12) : "l"(plo));
            asm("add.rn.f32x2 %0,%0,%1;" : "+l"(S01) : "l"(phi));
            asm("fma.rn.f32x2 %0,%1,%1,%0;" : "+l"(Q12) : "l"(plo));
            asm("fma.rn.f32x2 %0,%1,%1,%0;" : "+l"(Q01) : "l"(phi));
        } else {                 // pairs (2,0),(1,2)
            asm("add.rn.f32x2 %0,%0,%1;" : "+l"(S20) : "l"(plo));
            asm("add.rn.f32x2 %0,%0,%1;" : "+l"(S12) : "l"(phi));
            asm("fma.rn.f32x2 %0,%1,%1,%0;" : "+l"(Q20) : "l"(plo));
            asm("fma.rn.f32x2 %0,%1,%1,%0;" : "+l"(Q12) : "l"(phi));
        }
    }

    // unpack: frame-dim sums  f0=S01.lo+S20.hi  f1=S01.hi+S12.lo  f2=S20.lo+S12.hi
    float a0l, a0h, a1l, a1h, a2l, a2h;
    asm("mov.b64 {%0,%1}, %2;" : "=f"(a0l), "=f"(a0h) : "l"(S01));
    asm("mov.b64 {%0,%1}, %2;" : "=f"(a1l), "=f"(a1h) : "l"(S20));
    asm("mov.b64 {%0,%1}, %2;" : "=f"(a2l), "=f"(a2h) : "l"(S12));
    float fs0 = a0l + a1h, fs1 = a0h + a2l, fs2 = a1l + a2h;
    asm("mov.b64 {%0,%1}, %2;" : "=f"(a0l), "=f"(a0h) : "l"(Q01));
    asm("mov.b64 {%0,%1}, %2;" : "=f"(a1l), "=f"(a1h) : "l"(Q20));
    asm("mov.b64 {%0,%1}, %2;" : "=f"(a2l), "=f"(a2h) : "l"(Q12));
    float fq0 = a0l + a1h, fq1 = a0h + a2l, fq2 = a1l + a2h;

    // un-rotate: frame slot f holds actual dim (f+delta)%3
    float s0 = delta ? fs2 : fs0;
    float s1 = delta ? fs0 : fs1;
    float s2 = delta ? fs1 : fs2;
    float q0 = delta ? fq2 : fq0;
    float q1 = delta ? fq0 : fq1;
    float q2 = delta ? fq1 : fq2;

    // 8-lane group reduce (threads 8p..8p+7 own patch p of this half)
#pragma unroll
    for (int off = 4; off; off >>= 1) {
        s0 += __shfl_xor_sync(0xFFFFFFFFu, s0, off);
        s1 += __shfl_xor_sync(0xFFFFFFFFu, s1, off);
        s2 += __shfl_xor_sync(0xFFFFFFFFu, s2, off);
        q0 += __shfl_xor_sync(0xFFFFFFFFu, q0, off);
        q1 += __shfl_xor_sync(0xFFFFFFFFu, q1, off);
        q2 += __shfl_xor_sync(0xFFFFFFFFu, q2, off);
    }
    if ((tl & 7) == 0) {
        const int gp = half * 16 + (tl >> 3);
        const float inv_n = 1.0f / 64.0f;
        const float inv_nm1 = 1.0f / 63.0f;
        float m0 = s0 * inv_n, m1 = s1 * inv_n, m2 = s2 * inv_n;
        float sd0 = sqrt_approx(fmaxf((q0 - s0 * m0) * inv_nm1, 0.0f));
        float sd1 = sqrt_approx(fmaxf((q1 - s1 * m1) * inv_nm1, 0.0f));
        float sd2 = sqrt_approx(fmaxf((q2 - s2 * m2) * inv_nm1, 0.0f));
        s_lo[0 * NPATCH + gp] = m0 - sd0;
        s_lo[1 * NPATCH + gp] = m1 - sd1;
        s_lo[2 * NPATCH + gp] = m2 - sd2;
        s_hi[0 * NPATCH + gp] = m0 + sd0;
        s_hi[1 * NPATCH + gp] = m1 + sd1;
        s_hi[2 * NPATCH + gp] = m2 + sd2;
    }
    __syncthreads();

    // ---- Pair phase: full 32x32 symmetric; upper-tri incl diag =
    // 0.5*full + 0.5*diag -> weight 0.5 off-diag, 1.0 on diag.
    // j = lane stats hoisted to registers; i = warp + 8k uniform (broadcast LDS).
    const float jlo0 = s_lo[0 * NPATCH + lane];
    const float jlo1 = s_lo[1 * NPATCH + lane];
    const float jlo2 = s_lo[2 * NPATCH + lane];
    const float jhi0 = s_hi[0 * NPATCH + lane];
    const float jhi1 = s_hi[1 * NPATCH + lane];
    const float jhi2 = s_hi[2 * NPATCH + lane];

    float local = 0.0f;
#pragma unroll
    for (int k = 0; k < 4; k++) {
        const int i = warp + 8 * k;          // uniform within warp
        const float ilo0 = s_lo[0 * NPATCH + i];
        const float ilo1 = s_lo[1 * NPATCH + i];
        const float ilo2 = s_lo[2 * NPATCH + i];
        const float ihi0 = s_hi[0 * NPATCH + i];
        const float ihi1 = s_hi[1 * NPATCH + i];
        const float ihi2 = s_hi[2 * NPATCH + i];
        float r0 = fmaxf(fminf(ihi0 - jlo0, jhi0 - ilo0), 0.0f);
        float r1 = fmaxf(fminf(ihi1 - jlo1, jhi1 - ilo1), 0.0f);
        float r2 = fmaxf(fminf(ihi2 - jlo2, jhi2 - ilo2), 0.0f);
        float acc = fmaf(r0, r0, fmaf(r1, r1, r2 * r2));
        float nrm = sqrt_approx(acc);
        local += (i == lane) ? nrm : 0.5f * nrm;
    }

    // ---- Block reduce; CTA partial -> global scratch; last CTA finalizes ----
#pragma unroll
    for (int off = 16; off; off >>= 1)
        local += __shfl_xor_sync(0xFFFFFFFFu, local, off);
    if (lane == 0) s_part[warp] = local;
    __syncthreads();
    if (tid == 0) {
        float v = s_part[0] + s_part[1] + s_part[2] + s_part[3] +
                  s_part[4] + s_part[5] + s_part[6] + s_part[7];
        const float scale = 1.0f / (528.0f * (float)NBATCH);
        atomicAdd(&g_partial, v * scale);          // RED.ADD, no return
        // release-add on done counter: orders the partial add before the
        // count becomes visible; no membar, no L1 flush.
        unsigned int prev;
        asm volatile("atom.release.gpu.global.add.u32 %0, [%1], 1;"
                     : "=r"(prev) : "l"(&g_done) : "memory");
        if (prev == (unsigned int)(NBATCH - 1)) {
            float total;
            asm volatile("ld.acquire.gpu.global.f32 %0, [%1];"
                         : "=f"(total) : "l"(&g_partial) : "memory");
            out[0] = total;
            // reset scratch; kernel-boundary ordering covers the next replay
            g_partial = 0.0f;
            g_done = 0u;
        }
    }
}

extern "C" void kernel_launch(void* const* d_in, const int* in_sizes, int n_in,
                              void* d_out, int out_size) {
    const float* pcs = (const float*)d_in[0];
    float* out = (float*)d_out;
    prl_main_kernel<<<NBATCH, NTHREADS>>>(pcs, out);
}

// round 8
// speedup vs baseline: 1.0532x; 1.0211x over previous
#include <cuda_runtime.h>
#include <cstdint>
#include <math.h>

// PatchRepulsionLoss: pcs [8192, 2048, 3] f32 -> scalar f32
// B=8192, P=32 patches, n=64 pts/patch, N_SIGMA=1
// loss = sum_b sum_{i<=j} || relu(std_i+std_j - |mean_i-mean_j|) ||_2 / (528*B)
//
// Pair identity: std_i+std_j - |m_i-m_j| = min(hi_j - lo_i, hi_i - lo_j),
// hi = mean+std, lo = mean-std.
//
// Single-kernel: all CTAs contribute via fire-and-forget REDs (no returning
// atomics, no fences in the common path); block 8191 (dispatched last) polls
// the done-counter, writes d_out, and resets scratch for the next replay.

#define NPATCH 32
#define NBATCH 8192
#define NTHREADS 256
#define CHUNK_BYTES 12288            // 16 patches
#define BATCH_BYTES (2 * CHUNK_BYTES)

__device__ float g_partial;          // zero at load; reset by poller each run
__device__ unsigned int g_done;      // zero at load; reset by poller each run

__device__ __forceinline__ uint32_t smem_u32(const void* p) {
    uint32_t a;
    asm("{ .reg .u64 t; cvta.to.shared.u64 t, %1; cvt.u32.u64 %0, t; }"
        : "=r"(a) : "l"(p));
    return a;
}

__device__ __forceinline__ void bulk_copy(uint32_t dst, const void* src,
                                          uint32_t bytes, uint32_t mbar) {
    asm volatile("mbarrier.arrive.expect_tx.shared.b64 _, [%0], %1;"
                 :: "r"(mbar), "r"(bytes) : "memory");
    asm volatile(
        "cp.async.bulk.shared::cta.global.mbarrier::complete_tx::bytes "
        "[%0], [%1], %2, [%3];"
        :: "r"(dst), "l"(src), "r"(bytes), "r"(mbar) : "memory");
}

__device__ __forceinline__ void mbar_wait0(uint32_t mbar) {
    uint32_t done;
    asm volatile(
        "{\n\t.reg .pred p;\n\t"
        "mbarrier.try_wait.parity.acquire.cta.shared::cta.b64 p, [%1], 0;\n\t"
        "selp.b32 %0, 1, 0, p;\n\t}"
        : "=r"(done) : "r"(mbar) : "memory");
    if (!done) {
        asm volatile(
            "{\n\t.reg .pred P1;\n\t"
            "WL_%=:\n\t"
            "mbarrier.try_wait.parity.acquire.cta.shared::cta.b64 P1, [%0], 0, 0x989680;\n\t"
            "@P1 bra.uni WD_%=;\n\t"
            "bra.uni WL_%=;\n\t"
            "WD_%=:\n\t}"
            :: "r"(mbar) : "memory");
    }
}

__device__ __forceinline__ float sqrt_approx(float x) {
    float r;
    asm("sqrt.approx.f32 %0, %1;" : "=f"(r) : "f"(x));
    return r;
}

__global__ void __launch_bounds__(NTHREADS, 8)
prl_main_kernel(const float* __restrict__ pcs, float* __restrict__ out) {
    __shared__ alignas(128) float4 sbuf[1536];          // 24 KB, halves at 0/768
    __shared__ alignas(8) uint64_t mbar[2];
    __shared__ float s_lo[3 * NPATCH];                  // SoA [d][patch]
    __shared__ float s_hi[3 * NPATCH];
    __shared__ float s_part[8];

    const int tid = threadIdx.x;
    const int lane = tid & 31;
    const int warp = tid >> 5;
    const int half = tid >> 7;          // warps 0-3 -> chunk0, 4-7 -> chunk1
    const int tl = tid & 127;
    const uint32_t mb = smem_u32(&mbar[half]);
    const uint32_t sbase = smem_u32(sbuf);

    if (tid == 0) {
        asm volatile("mbarrier.init.shared.b64 [%0], 1;" :: "r"(smem_u32(&mbar[0])) : "memory");
        asm volatile("mbarrier.init.shared.b64 [%0], 1;" :: "r"(smem_u32(&mbar[1])) : "memory");
        const char* src = reinterpret_cast<const char*>(pcs) +
                          (size_t)blockIdx.x * BATCH_BYTES;
        bulk_copy(sbase, src, CHUNK_BYTES, smem_u32(&mbar[0]));
        bulk_copy(sbase + CHUNK_BYTES, src + CHUNK_BYTES, CHUNK_BYTES,
                  smem_u32(&mbar[1]));
    }
    __syncthreads();   // mbarrier inits visible before any wait

    mbar_wait0(mb);

    // ---- Stats: thread owns f4[6*tl .. 6*tl+5] of its half (24 consecutive
    // floats, phase 0). Loads permuted by delta=(lane>>2)&1 for bank-conflict
    // freedom; delta rotates the dim frame by +delta, undone via SELs below.
    const int delta = (lane >> 2) & 1;
    // packed accumulators: pair types (d0,d1),(d2,d0),(d1,d2) in delta-frame
    uint64_t S01 = 0, S20 = 0, S12 = 0;
    uint64_t Q01 = 0, Q20 = 0, Q12 = 0;
    const uint32_t tbase = sbase + (uint32_t)half * CHUNK_BYTES + (uint32_t)tl * 96;

#pragma unroll
    for (int j = 0; j < 6; j++) {
        int m = j + delta; if (m >= 6) m -= 6;
        uint64_t plo, phi;   // plo=(e0,e1), phi=(e2,e3); f4 start phase = j mod 3 (frame)
        asm("ld.shared.v2.b64 {%0,%1}, [%2];"
            : "=l"(plo), "=l"(phi) : "r"(tbase + (uint32_t)(m * 16)));
        if (j % 3 == 0) {      // pairs (0,1),(2,0)
            asm("add.rn.f32x2 %0,%0,%1;" : "+l"(S01) : "l"(plo));
            asm("add.rn.f32x2 %0,%0,%1;" : "+l"(S20) : "l"(phi));
            asm("fma.rn.f32x2 %0,%1,%1,%0;" : "+l"(Q01) : "l"(plo));
            asm("fma.rn.f32x2 %0,%1,%1,%0;" : "+l"(Q20) : "l"(phi));
        } else if (j % 3 == 1) { // pairs (1,2),(0,1)
            asm("add.rn.f32x2 %0,%0,%1;" : "+l"(S12) : "l"(plo));
            asm("add.rn.f32x2 %0,%0,%1;" : "+l"(S01) : "l"(phi));
            asm("fma.rn.f32x2 %0,%1,%1,%0;" : "+l"(Q12) : "l"(plo));
            asm("fma.rn.f32x2 %0,%1,%1,%0;" : "+l"(Q01) : "l"(phi));
        } else {                 // pairs (2,0),(1,2)
            asm("add.rn.f32x2 %0,%0,%1;" : "+l"(S20) : "l"(plo));
            asm("add.rn.f32x2 %0,%0,%1;" : "+l"(S12) : "l"(phi));
            asm("fma.rn.f32x2 %0,%1,%1,%0;" : "+l"(Q20) : "l"(plo));
            asm("fma.rn.f32x2 %0,%1,%1,%0;" : "+l"(Q12) : "l"(phi));
        }
    }

    // unpack: frame-dim sums  f0=S01.lo+S20.hi  f1=S01.hi+S12.lo  f2=S20.lo+S12.hi
    float a0l, a0h, a1l, a1h, a2l, a2h;
    asm("mov.b64 {%0,%1}, %2;" : "=f"(a0l), "=f"(a0h) : "l"(S01));
    asm("mov.b64 {%0,%1}, %2;" : "=f"(a1l), "=f"(a1h) : "l"(S20));
    asm("mov.b64 {%0,%1}, %2;" : "=f"(a2l), "=f"(a2h) : "l"(S12));
    float fs0 = a0l + a1h, fs1 = a0h + a2l, fs2 = a1l + a2h;
    asm("mov.b64 {%0,%1}, %2;" : "=f"(a0l), "=f"(a0h) : "l"(Q01));
    asm("mov.b64 {%0,%1}, %2;" : "=f"(a1l), "=f"(a1h) : "l"(Q20));
    asm("mov.b64 {%0,%1}, %2;" : "=f"(a2l), "=f"(a2h) : "l"(Q12));
    float fq0 = a0l + a1h, fq1 = a0h + a2l, fq2 = a1l + a2h;

    // un-rotate: frame slot f holds actual dim (f+delta)%3
    float s0 = delta ? fs2 : fs0;
    float s1 = delta ? fs0 : fs1;
    float s2 = delta ? fs1 : fs2;
    float q0 = delta ? fq2 : fq0;
    float q1 = delta ? fq0 : fq1;
    float q2 = delta ? fq1 : fq2;

    // 8-lane group reduce (threads 8p..8p+7 own patch p of this half)
#pragma unroll
    for (int off = 4; off; off >>= 1) {
        s0 += __shfl_xor_sync(0xFFFFFFFFu, s0, off);
        s1 += __shfl_xor_sync(0xFFFFFFFFu, s1, off);
        s2 += __shfl_xor_sync(0xFFFFFFFFu, s2, off);
        q0 += __shfl_xor_sync(0xFFFFFFFFu, q0, off);
        q1 += __shfl_xor_sync(0xFFFFFFFFu, q1, off);
        q2 += __shfl_xor_sync(0xFFFFFFFFu, q2, off);
    }
    if ((tl & 7) == 0) {
        const int gp = half * 16 + (tl >> 3);
        const float inv_n = 1.0f / 64.0f;
        const float inv_nm1 = 1.0f / 63.0f;
        float m0 = s0 * inv_n, m1 = s1 * inv_n, m2 = s2 * inv_n;
        float sd0 = sqrt_approx(fmaxf((q0 - s0 * m0) * inv_nm1, 0.0f));
        float sd1 = sqrt_approx(fmaxf((q1 - s1 * m1) * inv_nm1, 0.0f));
        float sd2 = sqrt_approx(fmaxf((q2 - s2 * m2) * inv_nm1, 0.0f));
        s_lo[0 * NPATCH + gp] = m0 - sd0;
        s_lo[1 * NPATCH + gp] = m1 - sd1;
        s_lo[2 * NPATCH + gp] = m2 - sd2;
        s_hi[0 * NPATCH + gp] = m0 + sd0;
        s_hi[1 * NPATCH + gp] = m1 + sd1;
        s_hi[2 * NPATCH + gp] = m2 + sd2;
    }
    __syncthreads();

    // ---- Pair phase: full 32x32 symmetric; upper-tri incl diag =
    // 0.5*full + 0.5*diag -> weight 0.5 off-diag, 1.0 on diag.
    // j = lane stats hoisted to registers; i = warp + 8k uniform (broadcast LDS).
    const float jlo0 = s_lo[0 * NPATCH + lane];
    const float jlo1 = s_lo[1 * NPATCH + lane];
    const float jlo2 = s_lo[2 * NPATCH + lane];
    const float jhi0 = s_hi[0 * NPATCH + lane];
    const float jhi1 = s_hi[1 * NPATCH + lane];
    const float jhi2 = s_hi[2 * NPATCH + lane];

    float local = 0.0f;
#pragma unroll
    for (int k = 0; k < 4; k++) {
        const int i = warp + 8 * k;          // uniform within warp
        const float ilo0 = s_lo[0 * NPATCH + i];
        const float ilo1 = s_lo[1 * NPATCH + i];
        const float ilo2 = s_lo[2 * NPATCH + i];
        const float ihi0 = s_hi[0 * NPATCH + i];
        const float ihi1 = s_hi[1 * NPATCH + i];
        const float ihi2 = s_hi[2 * NPATCH + i];
        float r0 = fmaxf(fminf(ihi0 - jlo0, jhi0 - ilo0), 0.0f);
        float r1 = fmaxf(fminf(ihi1 - jlo1, jhi1 - ilo1), 0.0f);
        float r2 = fmaxf(fminf(ihi2 - jlo2, jhi2 - ilo2), 0.0f);
        float acc = fmaf(r0, r0, fmaf(r1, r1, r2 * r2));
        float nrm = sqrt_approx(acc);
        local += (i == lane) ? nrm : 0.5f * nrm;
    }

    // ---- Block reduce; fire-and-forget REDs; block 8191 finalizes ----
#pragma unroll
    for (int off = 16; off; off >>= 1)
        local += __shfl_xor_sync(0xFFFFFFFFu, local, off);
    if (lane == 0) s_part[warp] = local;
    __syncthreads();
    if (tid == 0) {
        float v = s_part[0] + s_part[1] + s_part[2] + s_part[3] +
                  s_part[4] + s_part[5] + s_part[6] + s_part[7];
        const float scale = 1.0f / (528.0f * (float)NBATCH);
        // fire-and-forget: no return value, CTA retires immediately after
        asm volatile("red.global.add.f32 [%0], %1;"
                     :: "l"(&g_partial), "f"(v * scale) : "memory");
        if (blockIdx.x != (unsigned)(NBATCH - 1)) {
            // release-RED: orders the partial add before the count tick,
            // still fire-and-forget.
            asm volatile("red.release.gpu.global.add.u32 [%0], 1;"
                         :: "l"(&g_done) : "memory");
        } else {
            // poller: block 8191 (dispatched last) waits for the other 8191
            unsigned int cnt;
            do {
                asm volatile("ld.acquire.gpu.global.u32 %0, [%1];"
                             : "=r"(cnt) : "l"(&g_done) : "memory");
                if (cnt != (unsigned)(NBATCH - 1)) __nanosleep(128);
            } while (cnt != (unsigned)(NBATCH - 1));
            // own partial RED is same-thread same-address ordered; others'
            // are ordered by their release-REDs + our acquire loads.
            float total;
            asm volatile("ld.acquire.gpu.global.f32 %0, [%1];"
                         : "=f"(total) : "l"(&g_partial) : "memory");
            out[0] = total;                 // overwrites harness poison
            g_partial = 0.0f;               // reset for next graph replay
            g_done = 0u;
        }
    }
}

extern "C" void kernel_launch(void* const* d_in, const int* in_sizes, int n_in,
                              void* d_out, int out_size) {
    const float* pcs = (const float*)d_in[0];
    float* out = (float*)d_out;
    prl_main_kernel<<<NBATCH, NTHREADS>>>(pcs, out);
}

// round 9
// speedup vs baseline: 1.2183x; 1.1567x over previous
#include <cuda_runtime.h>
#include <cstdint>
#include <math.h>

// PatchRepulsionLoss: pcs [8192, 2048, 3] f32 -> scalar f32
// B=8192, P=32 patches, n=64 pts/patch, N_SIGMA=1
// loss = sum_b sum_{i<=j} || relu(std_i+std_j - |mean_i-mean_j|) ||_2 / (528*B)
//
// Pair identity: std_i+std_j - |m_i-m_j| = min(hi_j - lo_i, hi_i - lo_j),
// hi = mean+std, lo = mean-std.
//
// Two kernels, overlapped via PDL: the 1-thread zero kernel triggers early
// completion; the main grid launches concurrently and only gates its final
// atomicAdd on cudaGridDependencySynchronize().

#define NPATCH 32
#define NBATCH 8192
#define NTHREADS 256
#define CHUNK_BYTES 12288            // 16 patches
#define BATCH_BYTES (2 * CHUNK_BYTES)

__global__ void prl_zero_kernel(float* out) {
    out[0] = 0.0f;
    cudaTriggerProgrammaticLaunchCompletion();
}

__device__ __forceinline__ uint32_t smem_u32(const void* p) {
    uint32_t a;
    asm("{ .reg .u64 t; cvta.to.shared.u64 t, %1; cvt.u32.u64 %0, t; }"
        : "=r"(a) : "l"(p));
    return a;
}

__device__ __forceinline__ void bulk_copy(uint32_t dst, const void* src,
                                          uint32_t bytes, uint32_t mbar) {
    asm volatile("mbarrier.arrive.expect_tx.shared.b64 _, [%0], %1;"
                 :: "r"(mbar), "r"(bytes) : "memory");
    asm volatile(
        "cp.async.bulk.shared::cta.global.mbarrier::complete_tx::bytes "
        "[%0], [%1], %2, [%3];"
        :: "r"(dst), "l"(src), "r"(bytes), "r"(mbar) : "memory");
}

__device__ __forceinline__ void mbar_wait0(uint32_t mbar) {
    uint32_t done;
    asm volatile(
        "{\n\t.reg .pred p;\n\t"
        "mbarrier.try_wait.parity.acquire.cta.shared::cta.b64 p, [%1], 0;\n\t"
        "selp.b32 %0, 1, 0, p;\n\t}"
        : "=r"(done) : "r"(mbar) : "memory");
    if (!done) {
        asm volatile(
            "{\n\t.reg .pred P1;\n\t"
            "WL_%=:\n\t"
            "mbarrier.try_wait.parity.acquire.cta.shared::cta.b64 P1, [%0], 0, 0x989680;\n\t"
            "@P1 bra.uni WD_%=;\n\t"
            "bra.uni WL_%=;\n\t"
            "WD_%=:\n\t}"
            :: "r"(mbar) : "memory");
    }
}

__device__ __forceinline__ float sqrt_approx(float x) {
    float r;
    asm("sqrt.approx.f32 %0, %1;" : "=f"(r) : "f"(x));
    return r;
}

__global__ void __launch_bounds__(NTHREADS, 8)
prl_main_kernel(const float* __restrict__ pcs, float* __restrict__ out) {
    __shared__ alignas(128) float4 sbuf[1536];          // 24 KB, halves at 0/768
    __shared__ alignas(8) uint64_t mbar[2];
    __shared__ float s_lo[3 * NPATCH];                  // SoA [d][patch]
    __shared__ float s_hi[3 * NPATCH];
    __shared__ float s_part[8];

    const int tid = threadIdx.x;
    const int lane = tid & 31;
    const int warp = tid >> 5;
    const int half = tid >> 7;          // warps 0-3 -> chunk0, 4-7 -> chunk1
    const int tl = tid & 127;
    const uint32_t mb = smem_u32(&mbar[half]);
    const uint32_t sbase = smem_u32(sbuf);

    if (tid == 0) {
        asm volatile("mbarrier.init.shared.b64 [%0], 1;" :: "r"(smem_u32(&mbar[0])) : "memory");
        asm volatile("mbarrier.init.shared.b64 [%0], 1;" :: "r"(smem_u32(&mbar[1])) : "memory");
        const char* src = reinterpret_cast<const char*>(pcs) +
                          (size_t)blockIdx.x * BATCH_BYTES;
        bulk_copy(sbase, src, CHUNK_BYTES, smem_u32(&mbar[0]));
        bulk_copy(sbase + CHUNK_BYTES, src + CHUNK_BYTES, CHUNK_BYTES,
                  smem_u32(&mbar[1]));
    }
    __syncthreads();   // mbarrier inits visible before any wait

    mbar_wait0(mb);

    // ---- Stats: thread owns f4[6*tl .. 6*tl+5] of its half (24 consecutive
    // floats, phase 0). Loads permuted by delta=(lane>>2)&1 for bank-conflict
    // freedom; delta rotates the dim frame by +delta, undone via SELs below.
    const int delta = (lane >> 2) & 1;
    // packed accumulators: pair types (d0,d1),(d2,d0),(d1,d2) in delta-frame
    uint64_t S01 = 0, S20 = 0, S12 = 0;
    uint64_t Q01 = 0, Q20 = 0, Q12 = 0;
    const uint32_t tbase = sbase + (uint32_t)half * CHUNK_BYTES + (uint32_t)tl * 96;

#pragma unroll
    for (int j = 0; j < 6; j++) {
        int m = j + delta; if (m >= 6) m -= 6;
        uint64_t plo, phi;   // plo=(e0,e1), phi=(e2,e3); f4 start phase = j mod 3 (frame)
        asm("ld.shared.v2.b64 {%0,%1}, [%2];"
            : "=l"(plo), "=l"(phi) : "r"(tbase + (uint32_t)(m * 16)));
        if (j % 3 == 0) {      // pairs (0,1),(2,0)
            asm("add.rn.f32x2 %0,%0,%1;" : "+l"(S01) : "l"(plo));
            asm("add.rn.f32x2 %0,%0,%1;" : "+l"(S20) : "l"(phi));
            asm("fma.rn.f32x2 %0,%1,%1,%0;" : "+l"(Q01) : "l"(plo));
            asm("fma.rn.f32x2 %0,%1,%1,%0;" : "+l"(Q20) : "l"(phi));
        } else if (j % 3 == 1) { // pairs (1,2),(0,1)
            asm("add.rn.f32x2 %0,%0,%1;" : "+l"(S12) : "l"(plo));
            asm("add.rn.f32x2 %0,%0,%1;" : "+l"(S01) : "l"(phi));
            asm("fma.rn.f32x2 %0,%1,%1,%0;" : "+l"(Q12) : "l"(plo));
            asm("fma.rn.f32x2 %0,%1,%1,%0;" : "+l"(Q01) : "l"(phi));
        } else {                 // pairs (2,0),(1,2)
            asm("add.rn.f32x2 %0,%0,%1;" : "+l"(S20) : "l"(plo));
            asm("add.rn.f32x2 %0,%0,%1;" : "+l"(S12) : "l"(phi));
            asm("fma.rn.f32x2 %0,%1,%1,%0;" : "+l"(Q20) : "l"(plo));
            asm("fma.rn.f32x2 %0,%1,%1,%0;" : "+l"(Q12) : "l"(phi));
        }
    }

    // unpack: frame-dim sums  f0=S01.lo+S20.hi  f1=S01.hi+S12.lo  f2=S20.lo+S12.hi
    float a0l, a0h, a1l, a1h, a2l, a2h;
    asm("mov.b64 {%0,%1}, %2;" : "=f"(a0l), "=f"(a0h) : "l"(S01));
    asm("mov.b64 {%0,%1}, %2;" : "=f"(a1l), "=f"(a1h) : "l"(S20));
    asm("mov.b64 {%0,%1}, %2;" : "=f"(a2l), "=f"(a2h) : "l"(S12));
    float fs0 = a0l + a1h, fs1 = a0h + a2l, fs2 = a1l + a2h;
    asm("mov.b64 {%0,%1}, %2;" : "=f"(a0l), "=f"(a0h) : "l"(Q01));
    asm("mov.b64 {%0,%1}, %2;" : "=f"(a1l), "=f"(a1h) : "l"(Q20));
    asm("mov.b64 {%0,%1}, %2;" : "=f"(a2l), "=f"(a2h) : "l"(Q12));
    float fq0 = a0l + a1h, fq1 = a0h + a2l, fq2 = a1l + a2h;

    // un-rotate: frame slot f holds actual dim (f+delta)%3
    float s0 = delta ? fs2 : fs0;
    float s1 = delta ? fs0 : fs1;
    float s2 = delta ? fs1 : fs2;
    float q0 = delta ? fq2 : fq0;
    float q1 = delta ? fq0 : fq1;
    float q2 = delta ? fq1 : fq2;

    // 8-lane group reduce (threads 8p..8p+7 own patch p of this half)
#pragma unroll
    for (int off = 4; off; off >>= 1) {
        s0 += __shfl_xor_sync(0xFFFFFFFFu, s0, off);
        s1 += __shfl_xor_sync(0xFFFFFFFFu, s1, off);
        s2 += __shfl_xor_sync(0xFFFFFFFFu, s2, off);
        q0 += __shfl_xor_sync(0xFFFFFFFFu, q0, off);
        q1 += __shfl_xor_sync(0xFFFFFFFFu, q1, off);
        q2 += __shfl_xor_sync(0xFFFFFFFFu, q2, off);
    }
    if ((tl & 7) == 0) {
        const int gp = half * 16 + (tl >> 3);
        const float inv_n = 1.0f / 64.0f;
        const float inv_nm1 = 1.0f / 63.0f;
        float m0 = s0 * inv_n, m1 = s1 * inv_n, m2 = s2 * inv_n;
        float sd0 = sqrt_approx(fmaxf((q0 - s0 * m0) * inv_nm1, 0.0f));
        float sd1 = sqrt_approx(fmaxf((q1 - s1 * m1) * inv_nm1, 0.0f));
        float sd2 = sqrt_approx(fmaxf((q2 - s2 * m2) * inv_nm1, 0.0f));
        s_lo[0 * NPATCH + gp] = m0 - sd0;
        s_lo[1 * NPATCH + gp] = m1 - sd1;
        s_lo[2 * NPATCH + gp] = m2 - sd2;
        s_hi[0 * NPATCH + gp] = m0 + sd0;
        s_hi[1 * NPATCH + gp] = m1 + sd1;
        s_hi[2 * NPATCH + gp] = m2 + sd2;
    }
    __syncthreads();

    // ---- Pair phase: full 32x32 symmetric; upper-tri incl diag =
    // 0.5*full + 0.5*diag -> weight 0.5 off-diag, 1.0 on diag.
    // j = lane stats hoisted to registers; i = warp + 8k uniform (broadcast LDS).
    const float jlo0 = s_lo[0 * NPATCH + lane];
    const float jlo1 = s_lo[1 * NPATCH + lane];
    const float jlo2 = s_lo[2 * NPATCH + lane];
    const float jhi0 = s_hi[0 * NPATCH + lane];
    const float jhi1 = s_hi[1 * NPATCH + lane];
    const float jhi2 = s_hi[2 * NPATCH + lane];

    float local = 0.0f;
#pragma unroll
    for (int k = 0; k < 4; k++) {
        const int i = warp + 8 * k;          // uniform within warp
        const float ilo0 = s_lo[0 * NPATCH + i];
        const float ilo1 = s_lo[1 * NPATCH + i];
        const float ilo2 = s_lo[2 * NPATCH + i];
        const float ihi0 = s_hi[0 * NPATCH + i];
        const float ihi1 = s_hi[1 * NPATCH + i];
        const float ihi2 = s_hi[2 * NPATCH + i];
        float r0 = fmaxf(fminf(ihi0 - jlo0, jhi0 - ilo0), 0.0f);
        float r1 = fmaxf(fminf(ihi1 - jlo1, jhi1 - ilo1), 0.0f);
        float r2 = fmaxf(fminf(ihi2 - jlo2, jhi2 - ilo2), 0.0f);
        float acc = fmaf(r0, r0, fmaf(r1, r1, r2 * r2));
        float nrm = sqrt_approx(acc);
        local += (i == lane) ? nrm : 0.5f * nrm;
    }

    // ---- Block reduce + single fire-and-forget atomic ----
#pragma unroll
    for (int off = 16; off; off >>= 1)
        local += __shfl_xor_sync(0xFFFFFFFFu, local, off);
    if (lane == 0) s_part[warp] = local;
    __syncthreads();
    if (warp == 0) {
        float v = (lane < 8) ? s_part[lane] : 0.0f;
#pragma unroll
        for (int off = 4; off; off >>= 1)
            v += __shfl_xor_sync(0xFFFFFFFFu, v, off);
        if (lane == 0) {
            // gate only the out-access on the zero kernel (PDL); the zero
            // kernel is 1 thread and finished long ago -> wait is ~free.
            cudaGridDependencySynchronize();
            const float scale = 1.0f / (528.0f * (float)NBATCH);
            atomicAdd(out, v * scale);
        }
    }
}

extern "C" void kernel_launch(void* const* d_in, const int* in_sizes, int n_in,
                              void* d_out, int out_size) {
    const float* pcs = (const float*)d_in[0];
    float* out = (float*)d_out;

    prl_zero_kernel<<<1, 1>>>(out);

    cudaLaunchConfig_t cfg = {};
    cfg.gridDim = dim3(NBATCH, 1, 1);
    cfg.blockDim = dim3(NTHREADS, 1, 1);
    cfg.dynamicSmemBytes = 0;
    cfg.stream = 0;
    cudaLaunchAttribute attr[1];
    attr[0].id = cudaLaunchAttributeProgrammaticStreamSerialization;
    attr[0].val.programmaticStreamSerializationAllowed = 1;
    cfg.attrs = attr;
    cfg.numAttrs = 1;
    cudaLaunchKernelEx(&cfg, prl_main_kernel, pcs, out);
}